// round 16
// baseline (speedup 1.0000x reference)
#include <cuda_runtime.h>
#include <cuda_bf16.h>

// Edge rows of pooled diff tiles (only rows r==0,3 of each 4-row group are
// read by K2; rest of the array is dead). 2 MB static scratch.
__device__ float g_diff[32 * 128 * 128];

// K1: pooled diff + ALL TV terms local to a 4-row x 128-col tile.
// grid = (32 row-groups, 32 batch), block = 512 (one thread per pooled pixel).
// Same coalesced float4 read pattern as the proven HBM-ceiling config.
// Local TV terms (horizontal + intra-tile vertical + image-edge zero-pad)
// block-reduced and atomicAdd'ed into out (zeroed by a memset node BEFORE
// this kernel -- in-kernel zeroing raced with other blocks' atomics in R15).
__global__ __launch_bounds__(512) void pool_tv_kernel(
    const float* __restrict__ org, const float* __restrict__ enh,
    float* __restrict__ out)
{
    asm volatile("griddepcontrol.launch_dependents;" ::: "memory");

    const int t = threadIdx.x;        // 0..511
    const int r = t >> 7;             // row within group 0..3
    const int x = t & 127;            // pooled col
    const int g = blockIdx.x;         // row group 0..31
    const int b = blockIdx.y;         // batch 0..31
    const int py = (g << 2) + r;      // pooled row 0..127

    float s = 0.f;
#pragma unroll
    for (int c = 0; c < 3; ++c) {
#pragma unroll
        for (int dy = 0; dy < 4; ++dy) {
            const size_t off = (((size_t)(b * 3 + c) * 512) + (size_t)(py * 4 + dy)) * 512
                               + (size_t)(4 * x);
            const float4 o = *reinterpret_cast<const float4*>(org + off);
            const float4 e = *reinterpret_cast<const float4*>(enh + off);
            s += (o.x - e.x) + (o.y - e.y) + (o.z - e.z) + (o.w - e.w);
        }
    }
    const float d = s * (1.0f / 48.0f);   // /(3ch * 16px)

    __shared__ float tile[4][128];
    tile[r][x] = d;
    // Only tile edge rows are needed by K2 (cross-boundary terms).
    if (r == 0 || r == 3)
        g_diff[(b << 14) + (py << 7) + x] = d;
    __syncthreads();

    // Local TV terms for this pixel (zero padding at image borders).
    float v = 0.f, a;
    const float l  = (x > 0)   ? tile[r][x - 1] : 0.f;
    const float rt = (x < 127) ? tile[r][x + 1] : 0.f;
    a = d - l;  v += a * a;
    a = d - rt; v += a * a;

    if (r > 0)       { a = d - tile[r - 1][x]; v += a * a; }
    else if (g == 0) { v += d * d; }           // up-term vs zero pad
    // (g>0, r==0: cross-tile up-term -> K2)

    if (r < 3)        { a = d - tile[r + 1][x]; v += a * a; }
    else if (g == 31) { v += d * d; }          // down-term vs zero pad
    // (g<31, r==3: cross-tile down-term -> K2)

    // block reduce (16 warps)
#pragma unroll
    for (int o = 16; o > 0; o >>= 1)
        v += __shfl_xor_sync(0xFFFFFFFFu, v, o);

    __shared__ float ws[16];
    if ((t & 31) == 0) ws[t >> 5] = v;
    __syncthreads();

    if (t < 32) {
        float vv = (t < 16) ? ws[t] : 0.f;
#pragma unroll
        for (int o = 8; o > 0; o >>= 1)
            vv += __shfl_xor_sync(0xFFFFFFFFu, vv, o);
        if (t == 0)
            atomicAdd(out, vv * (1.0f / (32.0f * 128.0f * 128.0f)));
    }
}

// K2: cross-tile boundary terms only. For each image b and interior boundary
// k=1..31: rows 4k and 4k-1 contribute 2*(d[4k][x]-d[4k-1][x])^2 (the up-term
// at 4k plus the identical down-term at 4k-1). One thread per float4 column
// quad: 32 b * 31 k * 32 quads = 31744 threads = 124 blocks x 256. PDL.
__global__ __launch_bounds__(256) void boundary_kernel(float* __restrict__ out)
{
    const int idx = blockIdx.x * 256 + threadIdx.x;   // 0..31743
    const int b   = idx / 992;            // 31*32 quads per image
    const int rem = idx - b * 992;
    const int k   = rem >> 5;             // 0..30 -> boundary k+1
    const int xq  = rem & 31;             // float4 quad 0..31

    const int row_lo = ((k << 2) + 3);    // 4(k+1)-1
    const int row_hi = row_lo + 1;        // 4(k+1)
    const float* __restrict__ img = g_diff + ((size_t)b << 14);
    const int plo = (row_lo << 7) + (xq << 2);
    const int phi = (row_hi << 7) + (xq << 2);

    asm volatile("griddepcontrol.wait;" ::: "memory");

    const float4 lo = *reinterpret_cast<const float4*>(img + plo);
    const float4 hi = *reinterpret_cast<const float4*>(img + phi);

    float v, a;
    a = hi.x - lo.x; v  = a * a;
    a = hi.y - lo.y; v += a * a;
    a = hi.z - lo.z; v += a * a;
    a = hi.w - lo.w; v += a * a;
    v *= 2.0f;   // up-term + equal down-term

#pragma unroll
    for (int o = 16; o > 0; o >>= 1)
        v += __shfl_xor_sync(0xFFFFFFFFu, v, o);

    __shared__ float ws[8];
    if ((threadIdx.x & 31) == 0) ws[threadIdx.x >> 5] = v;
    __syncthreads();

    if (threadIdx.x < 32) {
        float vv = (threadIdx.x < 8) ? ws[threadIdx.x] : 0.f;
#pragma unroll
        for (int o = 4; o > 0; o >>= 1)
            vv += __shfl_xor_sync(0xFFFFFFFFu, vv, o);
        if (threadIdx.x == 0)
            atomicAdd(out, vv * (1.0f / (32.0f * 128.0f * 128.0f)));
    }
}

extern "C" void kernel_launch(void* const* d_in, const int* in_sizes, int n_in,
                              void* d_out, int out_size)
{
    const float* org = (const float*)d_in[0];
    const float* enh = (const float*)d_in[1];
    float* out = (float*)d_out;

    // Stream-ordered zero BEFORE any accumulating kernel (graph memset node).
    cudaMemsetAsync(out, 0, sizeof(float));

    dim3 g1(32, 32);
    pool_tv_kernel<<<g1, 512>>>(org, enh, out);

    cudaLaunchConfig_t cfg = {};
    cfg.gridDim  = dim3(124, 1, 1);
    cfg.blockDim = dim3(256, 1, 1);
    cfg.dynamicSmemBytes = 0;
    cfg.stream = 0;

    cudaLaunchAttribute attr[1];
    attr[0].id = cudaLaunchAttributeProgrammaticStreamSerialization;
    attr[0].val.programmaticStreamSerializationAllowed = 1;
    cfg.attrs = attr;
    cfg.numAttrs = 1;

    cudaLaunchKernelEx(&cfg, boundary_kernel, out);
}

// round 17
// speedup vs baseline: 1.1153x; 1.1153x over previous
#include <cuda_runtime.h>
#include <cuda_bf16.h>

// FINAL CONFIG (best measured: 35.3us; noise band ~1.5us).
// K1 (~32us): HBM-bound pooled diff at the streaming ceiling (~6.2 TB/s, 73%
//   of spec). Plain LDG.128. Rejected by measurement: __ldcs (-1.4us), MLP
//   restructure (neutral), in-kernel TV epilogue (+3.5us).
// K2 (~3us exposed): TV reduction under PDL; 512x256 measured best.
// Rejected wholesale: persistent fusion (static barrier 37.9, work stealing
//   45.6, last-finisher 38.9), boundary decomposition (41.2).

// Scratch for pooled diff: [32, 128, 128] floats = 2 MB (static, no allocs).
__device__ float g_diff[32 * 128 * 128];

// K1: pooled diff. grid = (128 pooled rows, 32 batch), block = 128 threads
// (one thread per pooled column). Each thread reads 3 channels x 4 rows x
// float4 (its 4x4 block, all channels) from BOTH tensors -> 24 x 16B loads,
// fully coalesced across the warp (512B contiguous per warp per load step).
__global__ __launch_bounds__(128) void pool_diff_kernel(
    const float* __restrict__ org, const float* __restrict__ enh,
    float* __restrict__ out)
{
    // Allow the dependent kernel (K2) to begin launching early (PDL).
    asm volatile("griddepcontrol.launch_dependents;" ::: "memory");

    const int t  = threadIdx.x;   // pooled col 0..127
    const int py = blockIdx.x;    // pooled row 0..127
    const int b  = blockIdx.y;    // batch 0..31

    // Safe: the only other writers of out[] are in K2, which is ordered
    // after K1 by griddepcontrol.wait.
    if (py == 0 && b == 0 && t == 0) out[0] = 0.f;

    float s = 0.f;
#pragma unroll
    for (int c = 0; c < 3; ++c) {
#pragma unroll
        for (int dy = 0; dy < 4; ++dy) {
            const size_t off = (((size_t)(b * 3 + c) * 512) + (size_t)(py * 4 + dy)) * 512
                               + (size_t)(4 * t);
            const float4 o = *reinterpret_cast<const float4*>(org + off);
            const float4 e = *reinterpret_cast<const float4*>(enh + off);
            s += (o.x - e.x) + (o.y - e.y) + (o.z - e.z) + (o.w - e.w);
        }
    }
    // mean over 3 channels and 16 pixels = /48
    g_diff[((b << 7) + py) * 128 + t] = s * (1.0f / 48.0f);
}

// K2: 4-direction shift-diff^2 + full reduction, vectorized (1 thread = one
// 4-wide row segment). 512 blocks x 256 threads = 131072 threads = NSEG.
// Launched with programmatic stream serialization: prologue overlaps K1.
__global__ __launch_bounds__(256) void tv_reduce_kernel(float* __restrict__ out)
{
    const int idx = blockIdx.x * 256 + threadIdx.x;   // 0 .. 131071
    const int b   = idx >> 12;        // 4096 segments per image
    const int r   = idx & 4095;
    const int y   = r >> 5;           // row 0..127
    const int sx  = (r & 31) << 2;    // segment start col: 0,4,...,124

    const float* __restrict__ img = g_diff + ((size_t)b << 14);
    const int p = (y << 7) + sx;

    // Wait for K1's memory to be visible before reading g_diff / out.
    asm volatile("griddepcontrol.wait;" ::: "memory");

    const float4 c  = *reinterpret_cast<const float4*>(img + p);
    const float  l  = (sx > 0)   ? img[p - 1] : 0.f;
    const float  rr = (sx < 124) ? img[p + 4] : 0.f;

    float4 u, dn;
    if (y > 0)   u  = *reinterpret_cast<const float4*>(img + p - 128);
    else         u  = make_float4(0.f, 0.f, 0.f, 0.f);
    if (y < 127) dn = *reinterpret_cast<const float4*>(img + p + 128);
    else         dn = make_float4(0.f, 0.f, 0.f, 0.f);

    float v;
    {
        float a;
        a = c.x - l;    v  = a * a;
        a = c.x - c.y;  v += a * a;
        a = c.x - u.x;  v += a * a;
        a = c.x - dn.x; v += a * a;

        a = c.y - c.x;  v += a * a;
        a = c.y - c.z;  v += a * a;
        a = c.y - u.y;  v += a * a;
        a = c.y - dn.y; v += a * a;

        a = c.z - c.y;  v += a * a;
        a = c.z - c.w;  v += a * a;
        a = c.z - u.z;  v += a * a;
        a = c.z - dn.z; v += a * a;

        a = c.w - c.z;  v += a * a;
        a = c.w - rr;   v += a * a;
        a = c.w - u.w;  v += a * a;
        a = c.w - dn.w; v += a * a;
    }

    // warp reduce
#pragma unroll
    for (int o = 16; o > 0; o >>= 1)
        v += __shfl_xor_sync(0xFFFFFFFFu, v, o);

    __shared__ float ws[8];
    if ((threadIdx.x & 31) == 0) ws[threadIdx.x >> 5] = v;
    __syncthreads();

    if (threadIdx.x < 32) {
        float vv = (threadIdx.x < 8) ? ws[threadIdx.x] : 0.f;
#pragma unroll
        for (int o = 4; o > 0; o >>= 1)
            vv += __shfl_xor_sync(0xFFFFFFFFu, vv, o);
        if (threadIdx.x == 0)
            atomicAdd(out, vv * (1.0f / (32.0f * 128.0f * 128.0f)));
    }
}

extern "C" void kernel_launch(void* const* d_in, const int* in_sizes, int n_in,
                              void* d_out, int out_size)
{
    const float* org = (const float*)d_in[0];
    const float* enh = (const float*)d_in[1];
    float* out = (float*)d_out;

    dim3 g1(128, 32);
    pool_diff_kernel<<<g1, 128>>>(org, enh, out);

    // K2 with programmatic dependent launch: spins up during K1, waits for
    // K1's completion inside the kernel (griddepcontrol.wait).
    cudaLaunchConfig_t cfg = {};
    cfg.gridDim  = dim3(512, 1, 1);
    cfg.blockDim = dim3(256, 1, 1);
    cfg.dynamicSmemBytes = 0;
    cfg.stream = 0;

    cudaLaunchAttribute attr[1];
    attr[0].id = cudaLaunchAttributeProgrammaticStreamSerialization;
    attr[0].val.programmaticStreamSerializationAllowed = 1;
    cfg.attrs = attr;
    cfg.numAttrs = 1;

    cudaLaunchKernelEx(&cfg, tv_reduce_kernel, out);
}